// round 12
// baseline (speedup 1.0000x reference)
#include <cuda_runtime.h>
#include <cuda_bf16.h>
#include <cstdint>

#define N_NODES 100000
#define N_EDGES 400000
#define HID 128
#define HEADS 4
#define N_GRAPHS 2000
#define NEG_SLOPE 0.2f
#define BN_EPS 1e-5f
#define N_ITEMS (N_EDGES + N_NODES)   // edges + self loops

#define SCAN_B 512
#define SCAN_NB ((N_NODES + SCAN_B - 1) / SCAN_B)

// ---------------- scratch (static device globals; no runtime alloc) ----------
__device__ int   g_degi[N_NODES];
__device__ float g_dinv[N_NODES];
__device__ int   g_off[N_NODES + 1];
__device__ int   g_bsum[SCAN_NB];
__device__ int   g_epos[N_NODES];
__device__ int   g_esrc[N_ITEMS];
__device__ float g_h[(size_t)N_NODES * HID];
__device__ float g_t[(size_t)N_NODES * HID];
__device__ float g_hh[(size_t)N_NODES * HEADS * HID];
__device__ float g_as[(size_t)N_NODES * HEADS];
__device__ float g_ad[(size_t)N_NODES * HEADS];

// ---------------- degree + CSR build -----------------------------------------
__global__ void deg_init_kernel() {
    int i = blockIdx.x * blockDim.x + threadIdx.x;
    if (i < N_NODES) g_degi[i] = 1;
}
__global__ void deg_accum_kernel(const int* __restrict__ dst) {
    int e = blockIdx.x * blockDim.x + threadIdx.x;
    if (e < N_EDGES) atomicAdd(&g_degi[dst[e]], 1);
}
__global__ void deg_finish_kernel() {
    int i = blockIdx.x * blockDim.x + threadIdx.x;
    if (i < N_NODES) g_dinv[i] = rsqrtf((float)g_degi[i]);
}
__global__ void scan_block_kernel() {
    __shared__ int sh[SCAN_B];
    int tid = threadIdx.x;
    int i = blockIdx.x * SCAN_B + tid;
    int v = (i < N_NODES) ? g_degi[i] : 0;
    sh[tid] = v;
    __syncthreads();
#pragma unroll
    for (int off = 1; off < SCAN_B; off <<= 1) {
        int t = (tid >= off) ? sh[tid - off] : 0;
        __syncthreads();
        sh[tid] += t;
        __syncthreads();
    }
    if (i < N_NODES) g_off[i + 1] = sh[tid];
    if (tid == SCAN_B - 1) g_bsum[blockIdx.x] = sh[tid];
}
__global__ void scan_bsums_kernel() {
    if (threadIdx.x == 0 && blockIdx.x == 0) {
        int run = 0;
        for (int b = 0; b < SCAN_NB; b++) { int t = g_bsum[b]; g_bsum[b] = run; run += t; }
    }
}
__global__ void scan_add_kernel() {
    int tid = threadIdx.x;
    int i = blockIdx.x * SCAN_B + tid;
    if (i < N_NODES) g_off[i + 1] += g_bsum[blockIdx.x];
    if (i == 0) g_off[0] = 0;
}
__global__ void fill_self_kernel() {
    int d = blockIdx.x * blockDim.x + threadIdx.x;
    if (d < N_NODES) {
        int o = g_off[d];
        g_esrc[o] = d;
        g_epos[d] = o + 1;
    }
}
__global__ void fill_edges_kernel(const int* __restrict__ src, const int* __restrict__ dst) {
    int e = blockIdx.x * blockDim.x + threadIdx.x;
    if (e < N_EDGES) {
        int pos = atomicAdd(&g_epos[dst[e]], 1);
        g_esrc[pos] = src[e];
    }
}

// ---------------- mma.sync tf32 helpers ---------------------------------------
__device__ __forceinline__ uint32_t f2tf32(float f) {
    uint32_t u;
    asm("cvt.rna.tf32.f32 %0, %1;" : "=r"(u) : "f"(f));
    return u;
}
__device__ __forceinline__ void mma16n8k8(float* c, const uint4& a, const uint2& b) {
    asm volatile(
        "mma.sync.aligned.m16n8k8.row.col.f32.tf32.tf32.f32 "
        "{%0,%1,%2,%3}, {%4,%5,%6,%7}, {%8,%9}, {%0,%1,%2,%3};"
        : "+f"(c[0]), "+f"(c[1]), "+f"(c[2]), "+f"(c[3])
        : "r"(a.x), "r"(a.y), "r"(a.z), "r"(a.w), "r"(b.x), "r"(b.y));
}

// Padded block strides (floats) to avoid writer bank conflicts:
//   A: 8 m-tiles x 16 ksteps, 128 payload + 4 pad = 132 each
//   B: 16 n-tiles x 16 ksteps, 64 payload + 2 pad = 66 each
#define SA_STRIDE 132
#define SB_STRIDE 66
#define SM_A   0
#define SM_B   (128 * SA_STRIDE)                 // 16896
#define SM_ATT (SM_B + 256 * SB_STRIDE)          // 33792
#define SMEM_FLOATS (SM_ATT + 1024)
#define SMEM_BYTES  (SMEM_FLOATS * 4)

// ---------------- tensor-core GEMM:  Out[N,C] = A[N,128] @ W[128,C] ----------
// CTA: 128 rows x 128 cols, K=128 resident. 8 warps, each 64x32 (4x4 m16n8k8).
// Fragment-permuted SMEM: thread's A frag = contiguous uint4, B frag = uint2.
template <int C, bool FUSE_ATT>
__global__ void __launch_bounds__(256, 1) gemm_mma(
    const float* __restrict__ A, const float* __restrict__ W, float* __restrict__ Out,
    const float* __restrict__ att_src, const float* __restrict__ att_dst,
    float* __restrict__ as_out, float* __restrict__ ad_out) {
    extern __shared__ float smem[];
    const int tid = threadIdx.x;
    const int wid = tid >> 5;
    const int lane = tid & 31;
    const int g = lane >> 2;      // group id 0..7
    const int tig = lane & 3;     // thread in group
    const int wm = wid & 1;       // warp row block (0/1 -> rows 0/64)
    const int wn = wid >> 1;      // warp col block (0..3 -> cols *32)
    const int row0 = blockIdx.x * 128;
    const int cb = blockIdx.y * 128;

    // ---- load A (128 rows x 128 k) into fragment-permuted layout ----
    // frag map (m16n8k8 tf32): a0=(g,tig) a1=(g+8,tig) a2=(g,tig+4) a3=(g+8,tig+4)
#pragma unroll
    for (int it = 0; it < 16; it++) {
        int f4 = tid + it * 256;
        int row = f4 >> 5;            // 0..127
        int kq = f4 & 31;             // float4 index along k
        int grow = row0 + row;
        float4 v = make_float4(0.f, 0.f, 0.f, 0.f);
        if (grow < N_NODES) v = *(const float4*)&A[(size_t)grow * 128 + kq * 4];
        int mt = row >> 4, r = row & 15, gg = r & 7, hi = r >> 3;
        int ks = kq >> 1, cg = kq & 1;
        int slot = hi + 2 * cg;
        uint32_t* base = (uint32_t*)&smem[SM_A + (mt * 16 + ks) * SA_STRIDE + gg * 16 + slot];
        base[0] = f2tf32(v.x); base[4] = f2tf32(v.y);
        base[8] = f2tf32(v.z); base[12] = f2tf32(v.w);
    }
    // ---- load B = W (128 k x 128 n slice) into fragment-permuted layout ----
    // frag map: b0=(k=tig, n=g), b1=(k=tig+4, n=g)
#pragma unroll
    for (int it = 0; it < 16; it++) {
        int f4 = tid + it * 256;
        int k = f4 >> 5;              // 0..127
        int nq = f4 & 31;             // float4 index along n
        float4 v = *(const float4*)&W[(size_t)k * C + cb + nq * 4];
        int ks = k >> 3, c = k & 7, tg = c & 3, slot = c >> 2;
        int nt = nq >> 1, ng = (nq & 1) * 4;
        uint32_t* base = (uint32_t*)&smem[SM_B + (nt * 16 + ks) * SB_STRIDE + ng * 8 + tg * 2 + slot];
        base[0] = f2tf32(v.x); base[8] = f2tf32(v.y);
        base[16] = f2tf32(v.z); base[24] = f2tf32(v.w);
    }
    __syncthreads();

    float acc[4][4][4];
#pragma unroll
    for (int mt = 0; mt < 4; mt++)
#pragma unroll
        for (int nt = 0; nt < 4; nt++)
#pragma unroll
            for (int j = 0; j < 4; j++) acc[mt][nt][j] = 0.f;

#pragma unroll 4
    for (int ks = 0; ks < 16; ks++) {
        uint4 a[4];
        uint2 b[4];
#pragma unroll
        for (int mt = 0; mt < 4; mt++)
            a[mt] = *(uint4*)&smem[SM_A + ((wm * 4 + mt) * 16 + ks) * SA_STRIDE + lane * 4];
#pragma unroll
        for (int nt = 0; nt < 4; nt++)
            b[nt] = *(uint2*)&smem[SM_B + ((wn * 4 + nt) * 16 + ks) * SB_STRIDE + lane * 2];
#pragma unroll
        for (int mt = 0; mt < 4; mt++)
#pragma unroll
            for (int nt = 0; nt < 4; nt++)
                mma16n8k8(acc[mt][nt], a[mt], b[nt]);
    }

    // ---- store C ----
#pragma unroll
    for (int mt = 0; mt < 4; mt++) {
        int r_lo = row0 + wm * 64 + mt * 16 + g;
        int r_hi = r_lo + 8;
#pragma unroll
        for (int nt = 0; nt < 4; nt++) {
            int col = cb + wn * 32 + nt * 8 + 2 * tig;
            if (r_lo < N_NODES)
                *(float2*)&Out[(size_t)r_lo * C + col] = make_float2(acc[mt][nt][0], acc[mt][nt][1]);
            if (r_hi < N_NODES)
                *(float2*)&Out[(size_t)r_hi * C + col] = make_float2(acc[mt][nt][2], acc[mt][nt][3]);
        }
    }

    if (FUSE_ATT) {
        const int head = blockIdx.y;
        const float* Ws = att_src + head * 128;
        const float* Wd = att_dst + head * 128;
#pragma unroll
        for (int mt = 0; mt < 4; mt++) {
            float ss0 = 0.f, sd0 = 0.f, ss1 = 0.f, sd1 = 0.f;
#pragma unroll
            for (int nt = 0; nt < 4; nt++) {
                int col = wn * 32 + nt * 8 + 2 * tig;
                float w0s = Ws[col], w1s = Ws[col + 1];
                float w0d = Wd[col], w1d = Wd[col + 1];
                ss0 += acc[mt][nt][0] * w0s + acc[mt][nt][1] * w1s;
                sd0 += acc[mt][nt][0] * w0d + acc[mt][nt][1] * w1d;
                ss1 += acc[mt][nt][2] * w0s + acc[mt][nt][3] * w1s;
                sd1 += acc[mt][nt][2] * w0d + acc[mt][nt][3] * w1d;
            }
#pragma unroll
            for (int o = 1; o <= 2; o <<= 1) {
                ss0 += __shfl_xor_sync(0xffffffffu, ss0, o);
                sd0 += __shfl_xor_sync(0xffffffffu, sd0, o);
                ss1 += __shfl_xor_sync(0xffffffffu, ss1, o);
                sd1 += __shfl_xor_sync(0xffffffffu, sd1, o);
            }
            if (tig == 0) {
                int r_lo = wm * 64 + mt * 16 + g;
                int r_hi = r_lo + 8;
                smem[SM_ATT + (r_lo * 4 + wn) * 2 + 0] = ss0;
                smem[SM_ATT + (r_lo * 4 + wn) * 2 + 1] = sd0;
                smem[SM_ATT + (r_hi * 4 + wn) * 2 + 0] = ss1;
                smem[SM_ATT + (r_hi * 4 + wn) * 2 + 1] = sd1;
            }
        }
        __syncthreads();
        if (tid < 128) {
            int grow = row0 + tid;
            if (grow < N_NODES) {
                float ss = 0.f, sd = 0.f;
#pragma unroll
                for (int w = 0; w < 4; w++) {
                    ss += smem[SM_ATT + (tid * 4 + w) * 2 + 0];
                    sd += smem[SM_ATT + (tid * 4 + w) * 2 + 1];
                }
                as_out[grow * HEADS + head] = ss;
                ad_out[grow * HEADS + head] = sd;
            }
        }
    }
}

// ---------------- GCN gather (CSR) + bias + BN + ReLU + residual -------------
__global__ void gcn_gather_kernel(const float* __restrict__ t,
                                  const float* __restrict__ b, const float* __restrict__ gamma,
                                  const float* __restrict__ beta, const float* __restrict__ mean,
                                  const float* __restrict__ var, int residual) {
    int warp = (blockIdx.x * blockDim.x + threadIdx.x) >> 5;
    int lane = threadIdx.x & 31;
    if (warp >= N_NODES) return;
    const int d = warp;
    const float dd = g_dinv[d];
    const int beg = g_off[d], end = g_off[d + 1];
    const int c = lane * 4;
    float4 acc = make_float4(0.f, 0.f, 0.f, 0.f);
    for (int i = beg; i < end; i++) {
        int s = g_esrc[i];
        float w = dd * g_dinv[s];
        float4 v = *(const float4*)&t[(size_t)s * HID + c];
        acc.x += v.x * w; acc.y += v.y * w; acc.z += v.z * w; acc.w += v.w * w;
    }
    float4 bb = *(const float4*)&b[c];
    float4 mm = *(const float4*)&mean[c];
    float4 vv = *(const float4*)&var[c];
    float4 gg = *(const float4*)&gamma[c];
    float4 be = *(const float4*)&beta[c];
    float4 r;
    r.x = fmaxf((acc.x + bb.x - mm.x) * rsqrtf(vv.x + BN_EPS) * gg.x + be.x, 0.f);
    r.y = fmaxf((acc.y + bb.y - mm.y) * rsqrtf(vv.y + BN_EPS) * gg.y + be.y, 0.f);
    r.z = fmaxf((acc.z + bb.z - mm.z) * rsqrtf(vv.z + BN_EPS) * gg.z + be.z, 0.f);
    r.w = fmaxf((acc.w + bb.w - mm.w) * rsqrtf(vv.w + BN_EPS) * gg.w + be.w, 0.f);
    float* hp = &g_h[(size_t)d * HID + c];
    if (residual) {
        float4 hv = *(const float4*)hp;
        r.x += hv.x; r.y += hv.y; r.z += hv.z; r.w += hv.w;
    }
    *(float4*)hp = r;
}

__device__ __forceinline__ float leaky(float x) { return x > 0.f ? x : NEG_SLOPE * x; }

// ---------------- GAT: softmax (max cancels) + weighted gather + bias --------
__global__ void gat_agg_kernel(const float* __restrict__ hh, const float* __restrict__ gat_b) {
    int warp = (blockIdx.x * blockDim.x + threadIdx.x) >> 5;
    int lane = threadIdx.x & 31;
    if (warp >= N_NODES) return;
    const int d = warp;
    const int beg = g_off[d], end = g_off[d + 1];
    const float4 ad4 = *(const float4*)&g_ad[(size_t)d * HEADS];

    float4 ds = make_float4(0.f, 0.f, 0.f, 0.f);
    for (int i = beg + lane; i < end; i += 32) {
        int s = g_esrc[i];
        float4 as4 = *(const float4*)&g_as[(size_t)s * HEADS];
        ds.x += expf(leaky(as4.x + ad4.x));
        ds.y += expf(leaky(as4.y + ad4.y));
        ds.z += expf(leaky(as4.z + ad4.z));
        ds.w += expf(leaky(as4.w + ad4.w));
    }
#pragma unroll
    for (int o = 16; o; o >>= 1) {
        ds.x += __shfl_xor_sync(0xffffffffu, ds.x, o);
        ds.y += __shfl_xor_sync(0xffffffffu, ds.y, o);
        ds.z += __shfl_xor_sync(0xffffffffu, ds.z, o);
        ds.w += __shfl_xor_sync(0xffffffffu, ds.w, o);
    }
    float4 rcp;
    rcp.x = 0.25f / (ds.x + 1e-16f);
    rcp.y = 0.25f / (ds.y + 1e-16f);
    rcp.z = 0.25f / (ds.z + 1e-16f);
    rcp.w = 0.25f / (ds.w + 1e-16f);

    const int c = lane * 4;
    float4 acc = make_float4(0.f, 0.f, 0.f, 0.f);
    for (int i = beg; i < end; i++) {
        int s = g_esrc[i];
        float4 as4 = *(const float4*)&g_as[(size_t)s * HEADS];
        float a0 = expf(leaky(as4.x + ad4.x)) * rcp.x;
        float a1 = expf(leaky(as4.y + ad4.y)) * rcp.y;
        float a2 = expf(leaky(as4.z + ad4.z)) * rcp.z;
        float a3 = expf(leaky(as4.w + ad4.w)) * rcp.w;
        const float* p = hh + (size_t)s * (HEADS * HID) + c;
        float4 v0 = *(const float4*)p;
        float4 v1 = *(const float4*)(p + HID);
        float4 v2 = *(const float4*)(p + 2 * HID);
        float4 v3 = *(const float4*)(p + 3 * HID);
        acc.x += a0 * v0.x + a1 * v1.x + a2 * v2.x + a3 * v3.x;
        acc.y += a0 * v0.y + a1 * v1.y + a2 * v2.y + a3 * v3.y;
        acc.z += a0 * v0.z + a1 * v1.z + a2 * v2.z + a3 * v3.z;
        acc.w += a0 * v0.w + a1 * v1.w + a2 * v2.w + a3 * v3.w;
    }
    float4 bv = *(const float4*)&gat_b[c];
    float* hp = &g_h[(size_t)d * HID + c];
    float4 hv = *(const float4*)hp;
    hv.x += acc.x + bv.x; hv.y += acc.y + bv.y;
    hv.z += acc.z + bv.z; hv.w += acc.w + bv.w;
    *(float4*)hp = hv;
}

// ---------------- pool (sorted batch -> ranges) + MLP ------------------------
__global__ void pool_mlp_kernel(const int* __restrict__ batch,
                                const float* __restrict__ c1W, const float* __restrict__ c1b,
                                const float* __restrict__ c2W, const float* __restrict__ c2b,
                                const float* __restrict__ c3W, const float* __restrict__ c3b,
                                float* __restrict__ out) {
    const int g = blockIdx.x;
    const int tid = threadIdx.x;   // 128 threads
    __shared__ int sbeg, send;
    __shared__ float gv[128];
    __shared__ float z1[64];
    __shared__ float z2[32];
    if (tid == 0) {
        int lo = 0, hi = N_NODES;
        while (lo < hi) { int mid = (lo + hi) >> 1; if (batch[mid] < g) lo = mid + 1; else hi = mid; }
        sbeg = lo;
        lo = sbeg; hi = N_NODES;
        while (lo < hi) { int mid = (lo + hi) >> 1; if (batch[mid] < g + 1) lo = mid + 1; else hi = mid; }
        send = lo;
    }
    __syncthreads();
    const int beg = sbeg, end = send;
    float s = 0.f;
    for (int r = beg; r < end; r++) s += g_h[(size_t)r * HID + tid];
    float cnt = fmaxf((float)(end - beg), 1.0f);
    gv[tid] = s / cnt;
    __syncthreads();
    if (tid < 64) {
        float z = c1b[tid];
#pragma unroll 8
        for (int k = 0; k < 128; k++) z += gv[k] * c1W[k * 64 + tid];
        z1[tid] = fmaxf(z, 0.f);
    }
    __syncthreads();
    if (tid < 32) {
        float z = c2b[tid];
#pragma unroll 8
        for (int k = 0; k < 64; k++) z += z1[k] * c2W[k * 32 + tid];
        z2[tid] = fmaxf(z, 0.f);
        __syncwarp();
        float p = z2[tid] * c3W[tid];
#pragma unroll
        for (int o = 16; o; o >>= 1) p += __shfl_xor_sync(0xffffffffu, p, o);
        if (tid == 0) out[g] = p + c3b[0];
    }
}

// -----------------------------------------------------------------------------
static inline int cdiv(long long a, int b) { return (int)((a + b - 1) / b); }

extern "C" void kernel_launch(void* const* d_in, const int* in_sizes, int n_in,
                              void* d_out, int out_size) {
    const float* x      = (const float*)d_in[0];
    const int*   ei     = (const int*)d_in[1];
    const int*   batch  = (const int*)d_in[2];
    const float* gcn_W  = (const float*)d_in[3];
    const float* gcn_b  = (const float*)d_in[4];
    const float* bn_g   = (const float*)d_in[5];
    const float* bn_bt  = (const float*)d_in[6];
    const float* bn_m   = (const float*)d_in[7];
    const float* bn_v   = (const float*)d_in[8];
    const float* gat_W  = (const float*)d_in[9];
    const float* att_s  = (const float*)d_in[10];
    const float* att_d  = (const float*)d_in[11];
    const float* gat_b  = (const float*)d_in[12];
    const float* c1W    = (const float*)d_in[13];
    const float* c1b    = (const float*)d_in[14];
    const float* c2W    = (const float*)d_in[15];
    const float* c2b    = (const float*)d_in[16];
    const float* c3W    = (const float*)d_in[17];
    const float* c3b    = (const float*)d_in[18];
    float* out = (float*)d_out;

    const int* src = ei;
    const int* dst = ei + N_EDGES;
    const int T = 256;

    float *p_h, *p_t, *p_hh, *p_as, *p_ad;
    cudaGetSymbolAddress((void**)&p_h, g_h);
    cudaGetSymbolAddress((void**)&p_t, g_t);
    cudaGetSymbolAddress((void**)&p_hh, g_hh);
    cudaGetSymbolAddress((void**)&p_as, g_as);
    cudaGetSymbolAddress((void**)&p_ad, g_ad);

    cudaFuncSetAttribute(gemm_mma<128, false>, cudaFuncAttributeMaxDynamicSharedMemorySize, SMEM_BYTES);
    cudaFuncSetAttribute(gemm_mma<512, true>,  cudaFuncAttributeMaxDynamicSharedMemorySize, SMEM_BYTES);

    // ---- CSR build (by dst) + dinv ----
    deg_init_kernel<<<cdiv(N_NODES, T), T>>>();
    deg_accum_kernel<<<cdiv(N_EDGES, T), T>>>(dst);
    deg_finish_kernel<<<cdiv(N_NODES, T), T>>>();
    scan_block_kernel<<<SCAN_NB, SCAN_B>>>();
    scan_bsums_kernel<<<1, 32>>>();
    scan_add_kernel<<<SCAN_NB, SCAN_B>>>();
    fill_self_kernel<<<cdiv(N_NODES, T), T>>>();
    fill_edges_kernel<<<cdiv(N_EDGES, T), T>>>(src, dst);

    const int warp_nodes_blocks = cdiv((long long)N_NODES * 32, T);
    const int mtiles = cdiv(N_NODES, 128);

    // ---- 3 GCN layers ----
    for (int layer = 0; layer < 3; layer++) {
        const float* A = (layer == 0) ? x : p_h;
        gemm_mma<128, false><<<dim3(mtiles, 1), 256, SMEM_BYTES>>>(
            A, gcn_W + (size_t)layer * 128 * 128, p_t, nullptr, nullptr, nullptr, nullptr);
        gcn_gather_kernel<<<warp_nodes_blocks, T>>>(
            p_t, gcn_b + layer * 128, bn_g + layer * 128, bn_bt + layer * 128,
            bn_m + layer * 128, bn_v + layer * 128, layer > 0);
    }

    // ---- GAT ----
    gemm_mma<512, true><<<dim3(mtiles, 4), 256, SMEM_BYTES>>>(
        p_h, gat_W, p_hh, att_s, att_d, p_as, p_ad);
    gat_agg_kernel<<<warp_nodes_blocks, T>>>(p_hh, gat_b);

    // ---- pool + classifier ----
    pool_mlp_kernel<<<N_GRAPHS, 128>>>(batch, c1W, c1b, c2W, c2b, c3W, c3b, out);
}

// round 15
// speedup vs baseline: 1.0669x; 1.0669x over previous
#include <cuda_runtime.h>
#include <cuda_bf16.h>
#include <cstdint>

#define N_NODES 100000
#define N_EDGES 400000
#define HID 128
#define HEADS 4
#define N_GRAPHS 2000
#define NEG_SLOPE 0.2f
#define BN_EPS 1e-5f
#define N_ITEMS (N_EDGES + N_NODES)   // edges + self loops

#define SCAN_B 512
#define SCAN_NB ((N_NODES + SCAN_B - 1) / SCAN_B)

// ---------------- scratch (static device globals; no runtime alloc) ----------
__device__ int   g_degi[N_NODES];
__device__ float g_dinv[N_NODES];
__device__ int   g_off[N_NODES + 1];
__device__ int   g_bsum[SCAN_NB];
__device__ int   g_epos[N_NODES];
__device__ int   g_esrc[N_ITEMS];
__device__ float g_h[(size_t)N_NODES * HID];
__device__ float g_t[(size_t)N_NODES * HID];
__device__ float g_hh[(size_t)N_NODES * HEADS * HID];
__device__ float g_as[(size_t)N_NODES * HEADS];
__device__ float g_ad[(size_t)N_NODES * HEADS];

// ---------------- degree + CSR build -----------------------------------------
__global__ void deg_init_kernel() {
    int i = blockIdx.x * blockDim.x + threadIdx.x;
    if (i < N_NODES) g_degi[i] = 1;
}
__global__ void deg_accum_kernel(const int* __restrict__ dst) {
    int e = blockIdx.x * blockDim.x + threadIdx.x;
    if (e < N_EDGES) atomicAdd(&g_degi[dst[e]], 1);
}
__global__ void deg_finish_kernel() {
    int i = blockIdx.x * blockDim.x + threadIdx.x;
    if (i < N_NODES) g_dinv[i] = rsqrtf((float)g_degi[i]);
}
__global__ void scan_block_kernel() {
    __shared__ int sh[SCAN_B];
    int tid = threadIdx.x;
    int i = blockIdx.x * SCAN_B + tid;
    int v = (i < N_NODES) ? g_degi[i] : 0;
    sh[tid] = v;
    __syncthreads();
#pragma unroll
    for (int off = 1; off < SCAN_B; off <<= 1) {
        int t = (tid >= off) ? sh[tid - off] : 0;
        __syncthreads();
        sh[tid] += t;
        __syncthreads();
    }
    if (i < N_NODES) g_off[i + 1] = sh[tid];
    if (tid == SCAN_B - 1) g_bsum[blockIdx.x] = sh[tid];
}
__global__ void scan_bsums_kernel() {
    if (threadIdx.x == 0 && blockIdx.x == 0) {
        int run = 0;
        for (int b = 0; b < SCAN_NB; b++) { int t = g_bsum[b]; g_bsum[b] = run; run += t; }
    }
}
__global__ void scan_add_kernel() {
    int tid = threadIdx.x;
    int i = blockIdx.x * SCAN_B + tid;
    if (i < N_NODES) g_off[i + 1] += g_bsum[blockIdx.x];
    if (i == 0) g_off[0] = 0;
}
__global__ void fill_self_kernel() {
    int d = blockIdx.x * blockDim.x + threadIdx.x;
    if (d < N_NODES) {
        int o = g_off[d];
        g_esrc[o] = d;
        g_epos[d] = o + 1;
    }
}
__global__ void fill_edges_kernel(const int* __restrict__ src, const int* __restrict__ dst) {
    int e = blockIdx.x * blockDim.x + threadIdx.x;
    if (e < N_EDGES) {
        int pos = atomicAdd(&g_epos[dst[e]], 1);
        g_esrc[pos] = src[e];
    }
}

// ---------------- mma.sync tf32 helpers ---------------------------------------
__device__ __forceinline__ uint32_t f2tf32(float f) {
    uint32_t u;
    asm("cvt.rna.tf32.f32 %0, %1;" : "=r"(u) : "f"(f));
    return u;
}
__device__ __forceinline__ void mma16n8k8(float* c, const uint4& a, const uint2& b) {
    asm volatile(
        "mma.sync.aligned.m16n8k8.row.col.f32.tf32.tf32.f32 "
        "{%0,%1,%2,%3}, {%4,%5,%6,%7}, {%8,%9}, {%0,%1,%2,%3};"
        : "+f"(c[0]), "+f"(c[1]), "+f"(c[2]), "+f"(c[3])
        : "r"(a.x), "r"(a.y), "r"(a.z), "r"(a.w), "r"(b.x), "r"(b.y));
}

// SMEM layout (floats):
//  B resident (all K):  16 n-tiles x 16 ksteps x 66 = 16896
//  A stage x2 (K=32):    8 m-tiles x  4 ksteps x 132 = 4224 each
//  ATT buffer: 1024
#define SB_STRIDE 66
#define SA_STRIDE 132
#define SM_B   0
#define SM_A0  16896
#define SM_A1  (16896 + 4224)
#define SM_ATT (16896 + 8448)
#define SMEM_FLOATS (SM_ATT + 1024)
#define SMEM_BYTES  (SMEM_FLOATS * 4)          // 105472 B -> 2 CTAs/SM

// ---------------- tensor-core GEMM:  Out[N,C] = A[N,128] @ W[128,C] ----------
// CTA: 128 rows x 128 cols. 256 threads, 2 CTAs/SM. B fully SMEM-resident;
// A double-buffered in 4 K-chunks of 32 with register prefetch.
template <int C, bool FUSE_ATT>
__global__ void __launch_bounds__(256, 2) gemm_mma(
    const float* __restrict__ A, const float* __restrict__ W, float* __restrict__ Out,
    const float* __restrict__ att_src, const float* __restrict__ att_dst,
    float* __restrict__ as_out, float* __restrict__ ad_out) {
    extern __shared__ float smem[];
    const int tid = threadIdx.x;
    const int wid = tid >> 5;
    const int lane = tid & 31;
    const int g = lane >> 2;      // group id 0..7
    const int tig = lane & 3;     // thread in group
    const int wm = wid & 1;       // warp row block (0/1 -> rows 0/64)
    const int wn = wid >> 1;      // warp col block (0..3 -> cols *32)
    const int row0 = blockIdx.x * 128;
    const int cb = blockIdx.y * 128;

    // ---- stage B (all 128 k x 128 n) once; frag map b0=(tig,g) b1=(tig+4,g) ----
#pragma unroll
    for (int it = 0; it < 16; it++) {
        int f4 = tid + it * 256;
        int k = f4 >> 5, nq = f4 & 31;
        float4 v = *(const float4*)&W[(size_t)k * C + cb + nq * 4];
        int ks = k >> 3, c = k & 7, tg = c & 3, slot = c >> 2;
        int nt = nq >> 1, ng = (nq & 1) * 4;
        uint32_t* b = (uint32_t*)&smem[SM_B + (nt * 16 + ks) * SB_STRIDE + ng * 8 + tg * 2 + slot];
        b[0] = f2tf32(v.x); b[8] = f2tf32(v.y);
        b[16] = f2tf32(v.z); b[24] = f2tf32(v.w);
    }

    // ---- A chunk helpers (K chunk = 32 = 8 float4 per row) ----
    float4 aR[4];
    auto ldgA = [&](int kc) {
#pragma unroll
        for (int it = 0; it < 4; it++) {
            int f4 = tid + it * 256;
            int row = f4 >> 3, kq = f4 & 7;
            int grow = row0 + row;
            aR[it] = (grow < N_NODES)
                ? *(const float4*)&A[(size_t)grow * 128 + (kc * 8 + kq) * 4]
                : make_float4(0.f, 0.f, 0.f, 0.f);
        }
    };
    // frag map a0=(g,tig) a1=(g+8,tig) a2=(g,tig+4) a3=(g+8,tig+4)
    auto stsA = [&](int st) {
        float* base_st = smem + (st ? SM_A1 : SM_A0);
#pragma unroll
        for (int it = 0; it < 4; it++) {
            int f4 = tid + it * 256;
            int row = f4 >> 3, kq = f4 & 7;
            int mt = row >> 4, r = row & 15, gg = r & 7, hi = r >> 3;
            int ksl = kq >> 1, cg = kq & 1, slot = hi + 2 * cg;
            uint32_t* b = (uint32_t*)&base_st[(mt * 4 + ksl) * SA_STRIDE + gg * 16 + slot];
            b[0] = f2tf32(aR[it].x); b[4] = f2tf32(aR[it].y);
            b[8] = f2tf32(aR[it].z); b[12] = f2tf32(aR[it].w);
        }
    };

    float acc[4][4][4];
#pragma unroll
    for (int mt = 0; mt < 4; mt++)
#pragma unroll
        for (int nt = 0; nt < 4; nt++)
#pragma unroll
            for (int j = 0; j < 4; j++) acc[mt][nt][j] = 0.f;

    auto compute = [&](int kc) {
        float* abase = smem + ((kc & 1) ? SM_A1 : SM_A0);
#pragma unroll
        for (int ks = 0; ks < 4; ks++) {
            uint4 a[4];
            uint2 b[4];
#pragma unroll
            for (int mt = 0; mt < 4; mt++)
                a[mt] = *(uint4*)&abase[((wm * 4 + mt) * 4 + ks) * SA_STRIDE + lane * 4];
#pragma unroll
            for (int nt = 0; nt < 4; nt++)
                b[nt] = *(uint2*)&smem[SM_B + ((wn * 4 + nt) * 16 + kc * 4 + ks) * SB_STRIDE + lane * 2];
#pragma unroll
            for (int mt = 0; mt < 4; mt++)
#pragma unroll
                for (int nt = 0; nt < 4; nt++)
                    mma16n8k8(acc[mt][nt], a[mt], b[nt]);
        }
    };

    // ---- pipelined mainloop: LDG(kc+2) overlaps compute(kc+1) ----
    ldgA(0);
    stsA(0);
    ldgA(1);
    __syncthreads();
#pragma unroll
    for (int kc = 0; kc < 4; kc++) {
        compute(kc);
        if (kc < 3) {
            stsA((kc + 1) & 1);
            __syncthreads();
            if (kc < 2) ldgA(kc + 2);
        }
    }

    // ---- store C ----
#pragma unroll
    for (int mt = 0; mt < 4; mt++) {
        int r_lo = row0 + wm * 64 + mt * 16 + g;
        int r_hi = r_lo + 8;
#pragma unroll
        for (int nt = 0; nt < 4; nt++) {
            int col = cb + wn * 32 + nt * 8 + 2 * tig;
            if (r_lo < N_NODES)
                *(float2*)&Out[(size_t)r_lo * C + col] = make_float2(acc[mt][nt][0], acc[mt][nt][1]);
            if (r_hi < N_NODES)
                *(float2*)&Out[(size_t)r_hi * C + col] = make_float2(acc[mt][nt][2], acc[mt][nt][3]);
        }
    }

    if (FUSE_ATT) {
        const int head = blockIdx.y;
        const float* Ws = att_src + head * 128;
        const float* Wd = att_dst + head * 128;
#pragma unroll
        for (int mt = 0; mt < 4; mt++) {
            float ss0 = 0.f, sd0 = 0.f, ss1 = 0.f, sd1 = 0.f;
#pragma unroll
            for (int nt = 0; nt < 4; nt++) {
                int col = wn * 32 + nt * 8 + 2 * tig;
                float w0s = Ws[col], w1s = Ws[col + 1];
                float w0d = Wd[col], w1d = Wd[col + 1];
                ss0 += acc[mt][nt][0] * w0s + acc[mt][nt][1] * w1s;
                sd0 += acc[mt][nt][0] * w0d + acc[mt][nt][1] * w1d;
                ss1 += acc[mt][nt][2] * w0s + acc[mt][nt][3] * w1s;
                sd1 += acc[mt][nt][2] * w0d + acc[mt][nt][3] * w1d;
            }
#pragma unroll
            for (int o = 1; o <= 2; o <<= 1) {
                ss0 += __shfl_xor_sync(0xffffffffu, ss0, o);
                sd0 += __shfl_xor_sync(0xffffffffu, sd0, o);
                ss1 += __shfl_xor_sync(0xffffffffu, ss1, o);
                sd1 += __shfl_xor_sync(0xffffffffu, sd1, o);
            }
            if (tig == 0) {
                int r_lo = wm * 64 + mt * 16 + g;
                int r_hi = r_lo + 8;
                smem[SM_ATT + (r_lo * 4 + wn) * 2 + 0] = ss0;
                smem[SM_ATT + (r_lo * 4 + wn) * 2 + 1] = sd0;
                smem[SM_ATT + (r_hi * 4 + wn) * 2 + 0] = ss1;
                smem[SM_ATT + (r_hi * 4 + wn) * 2 + 1] = sd1;
            }
        }
        __syncthreads();
        if (tid < 128) {
            int grow = row0 + tid;
            if (grow < N_NODES) {
                float ss = 0.f, sd = 0.f;
#pragma unroll
                for (int w = 0; w < 4; w++) {
                    ss += smem[SM_ATT + (tid * 4 + w) * 2 + 0];
                    sd += smem[SM_ATT + (tid * 4 + w) * 2 + 1];
                }
                as_out[grow * HEADS + head] = ss;
                ad_out[grow * HEADS + head] = sd;
            }
        }
    }
}

// ---------------- GCN gather (CSR) + bias + BN + ReLU + residual -------------
__global__ void gcn_gather_kernel(const float* __restrict__ t,
                                  const float* __restrict__ b, const float* __restrict__ gamma,
                                  const float* __restrict__ beta, const float* __restrict__ mean,
                                  const float* __restrict__ var, int residual) {
    int warp = (blockIdx.x * blockDim.x + threadIdx.x) >> 5;
    int lane = threadIdx.x & 31;
    if (warp >= N_NODES) return;
    const int d = warp;
    const float dd = g_dinv[d];
    const int beg = g_off[d], end = g_off[d + 1];
    const int c = lane * 4;
    float4 acc = make_float4(0.f, 0.f, 0.f, 0.f);
    for (int i = beg; i < end; i++) {
        int s = g_esrc[i];
        float w = dd * g_dinv[s];
        float4 v = *(const float4*)&t[(size_t)s * HID + c];
        acc.x += v.x * w; acc.y += v.y * w; acc.z += v.z * w; acc.w += v.w * w;
    }
    float4 bb = *(const float4*)&b[c];
    float4 mm = *(const float4*)&mean[c];
    float4 vv = *(const float4*)&var[c];
    float4 gg = *(const float4*)&gamma[c];
    float4 be = *(const float4*)&beta[c];
    float4 r;
    r.x = fmaxf((acc.x + bb.x - mm.x) * rsqrtf(vv.x + BN_EPS) * gg.x + be.x, 0.f);
    r.y = fmaxf((acc.y + bb.y - mm.y) * rsqrtf(vv.y + BN_EPS) * gg.y + be.y, 0.f);
    r.z = fmaxf((acc.z + bb.z - mm.z) * rsqrtf(vv.z + BN_EPS) * gg.z + be.z, 0.f);
    r.w = fmaxf((acc.w + bb.w - mm.w) * rsqrtf(vv.w + BN_EPS) * gg.w + be.w, 0.f);
    float* hp = &g_h[(size_t)d * HID + c];
    if (residual) {
        float4 hv = *(const float4*)hp;
        r.x += hv.x; r.y += hv.y; r.z += hv.z; r.w += hv.w;
    }
    *(float4*)hp = r;
}

__device__ __forceinline__ float leaky(float x) { return x > 0.f ? x : NEG_SLOPE * x; }

// ---------------- GAT: softmax (max cancels) + weighted gather + bias --------
__global__ void gat_agg_kernel(const float* __restrict__ hh, const float* __restrict__ gat_b) {
    int warp = (blockIdx.x * blockDim.x + threadIdx.x) >> 5;
    int lane = threadIdx.x & 31;
    if (warp >= N_NODES) return;
    const int d = warp;
    const int beg = g_off[d], end = g_off[d + 1];
    const float4 ad4 = *(const float4*)&g_ad[(size_t)d * HEADS];

    float4 ds = make_float4(0.f, 0.f, 0.f, 0.f);
    for (int i = beg + lane; i < end; i += 32) {
        int s = g_esrc[i];
        float4 as4 = *(const float4*)&g_as[(size_t)s * HEADS];
        ds.x += expf(leaky(as4.x + ad4.x));
        ds.y += expf(leaky(as4.y + ad4.y));
        ds.z += expf(leaky(as4.z + ad4.z));
        ds.w += expf(leaky(as4.w + ad4.w));
    }
#pragma unroll
    for (int o = 16; o; o >>= 1) {
        ds.x += __shfl_xor_sync(0xffffffffu, ds.x, o);
        ds.y += __shfl_xor_sync(0xffffffffu, ds.y, o);
        ds.z += __shfl_xor_sync(0xffffffffu, ds.z, o);
        ds.w += __shfl_xor_sync(0xffffffffu, ds.w, o);
    }
    float4 rcp;
    rcp.x = 0.25f / (ds.x + 1e-16f);
    rcp.y = 0.25f / (ds.y + 1e-16f);
    rcp.z = 0.25f / (ds.z + 1e-16f);
    rcp.w = 0.25f / (ds.w + 1e-16f);

    const int c = lane * 4;
    float4 acc = make_float4(0.f, 0.f, 0.f, 0.f);
    for (int i = beg; i < end; i++) {
        int s = g_esrc[i];
        float4 as4 = *(const float4*)&g_as[(size_t)s * HEADS];
        float a0 = expf(leaky(as4.x + ad4.x)) * rcp.x;
        float a1 = expf(leaky(as4.y + ad4.y)) * rcp.y;
        float a2 = expf(leaky(as4.z + ad4.z)) * rcp.z;
        float a3 = expf(leaky(as4.w + ad4.w)) * rcp.w;
        const float* p = hh + (size_t)s * (HEADS * HID) + c;
        float4 v0 = *(const float4*)p;
        float4 v1 = *(const float4*)(p + HID);
        float4 v2 = *(const float4*)(p + 2 * HID);
        float4 v3 = *(const float4*)(p + 3 * HID);
        acc.x += a0 * v0.x + a1 * v1.x + a2 * v2.x + a3 * v3.x;
        acc.y += a0 * v0.y + a1 * v1.y + a2 * v2.y + a3 * v3.y;
        acc.z += a0 * v0.z + a1 * v1.z + a2 * v2.z + a3 * v3.z;
        acc.w += a0 * v0.w + a1 * v1.w + a2 * v2.w + a3 * v3.w;
    }
    float4 bv = *(const float4*)&gat_b[c];
    float* hp = &g_h[(size_t)d * HID + c];
    float4 hv = *(const float4*)hp;
    hv.x += acc.x + bv.x; hv.y += acc.y + bv.y;
    hv.z += acc.z + bv.z; hv.w += acc.w + bv.w;
    *(float4*)hp = hv;
}

// ---------------- pool (sorted batch -> ranges) + MLP ------------------------
__global__ void pool_mlp_kernel(const int* __restrict__ batch,
                                const float* __restrict__ c1W, const float* __restrict__ c1b,
                                const float* __restrict__ c2W, const float* __restrict__ c2b,
                                const float* __restrict__ c3W, const float* __restrict__ c3b,
                                float* __restrict__ out) {
    const int g = blockIdx.x;
    const int tid = threadIdx.x;   // 128 threads
    __shared__ int sbeg, send;
    __shared__ float gv[128];
    __shared__ float z1[64];
    __shared__ float z2[32];
    if (tid == 0) {
        int lo = 0, hi = N_NODES;
        while (lo < hi) { int mid = (lo + hi) >> 1; if (batch[mid] < g) lo = mid + 1; else hi = mid; }
        sbeg = lo;
        lo = sbeg; hi = N_NODES;
        while (lo < hi) { int mid = (lo + hi) >> 1; if (batch[mid] < g + 1) lo = mid + 1; else hi = mid; }
        send = lo;
    }
    __syncthreads();
    const int beg = sbeg, end = send;
    float s = 0.f;
    for (int r = beg; r < end; r++) s += g_h[(size_t)r * HID + tid];
    float cnt = fmaxf((float)(end - beg), 1.0f);
    gv[tid] = s / cnt;
    __syncthreads();
    if (tid < 64) {
        float z = c1b[tid];
#pragma unroll 8
        for (int k = 0; k < 128; k++) z += gv[k] * c1W[k * 64 + tid];
        z1[tid] = fmaxf(z, 0.f);
    }
    __syncthreads();
    if (tid < 32) {
        float z = c2b[tid];
#pragma unroll 8
        for (int k = 0; k < 64; k++) z += z1[k] * c2W[k * 32 + tid];
        z2[tid] = fmaxf(z, 0.f);
        __syncwarp();
        float p = z2[tid] * c3W[tid];
#pragma unroll
        for (int o = 16; o; o >>= 1) p += __shfl_xor_sync(0xffffffffu, p, o);
        if (tid == 0) out[g] = p + c3b[0];
    }
}

// -----------------------------------------------------------------------------
static inline int cdiv(long long a, int b) { return (int)((a + b - 1) / b); }

extern "C" void kernel_launch(void* const* d_in, const int* in_sizes, int n_in,
                              void* d_out, int out_size) {
    const float* x      = (const float*)d_in[0];
    const int*   ei     = (const int*)d_in[1];
    const int*   batch  = (const int*)d_in[2];
    const float* gcn_W  = (const float*)d_in[3];
    const float* gcn_b  = (const float*)d_in[4];
    const float* bn_g   = (const float*)d_in[5];
    const float* bn_bt  = (const float*)d_in[6];
    const float* bn_m   = (const float*)d_in[7];
    const float* bn_v   = (const float*)d_in[8];
    const float* gat_W  = (const float*)d_in[9];
    const float* att_s  = (const float*)d_in[10];
    const float* att_d  = (const float*)d_in[11];
    const float* gat_b  = (const float*)d_in[12];
    const float* c1W    = (const float*)d_in[13];
    const float* c1b    = (const float*)d_in[14];
    const float* c2W    = (const float*)d_in[15];
    const float* c2b    = (const float*)d_in[16];
    const float* c3W    = (const float*)d_in[17];
    const float* c3b    = (const float*)d_in[18];
    float* out = (float*)d_out;

    const int* src = ei;
    const int* dst = ei + N_EDGES;
    const int T = 256;

    float *p_h, *p_t, *p_hh, *p_as, *p_ad;
    cudaGetSymbolAddress((void**)&p_h, g_h);
    cudaGetSymbolAddress((void**)&p_t, g_t);
    cudaGetSymbolAddress((void**)&p_hh, g_hh);
    cudaGetSymbolAddress((void**)&p_as, g_as);
    cudaGetSymbolAddress((void**)&p_ad, g_ad);

    cudaFuncSetAttribute(gemm_mma<128, false>, cudaFuncAttributeMaxDynamicSharedMemorySize, SMEM_BYTES);
    cudaFuncSetAttribute(gemm_mma<512, true>,  cudaFuncAttributeMaxDynamicSharedMemorySize, SMEM_BYTES);

    const int warp_nodes_blocks = cdiv((long long)N_NODES * 32, T);
    const int mtiles = cdiv(N_NODES, 128);

    // ---- degrees (1-3), then GCN layer-0 GEMM as launch #4 (profiled) ----
    deg_init_kernel<<<cdiv(N_NODES, T), T>>>();
    deg_accum_kernel<<<cdiv(N_EDGES, T), T>>>(dst);
    deg_finish_kernel<<<cdiv(N_NODES, T), T>>>();
    gemm_mma<128, false><<<dim3(mtiles, 1), 256, SMEM_BYTES>>>(
        x, gcn_W, p_t, nullptr, nullptr, nullptr, nullptr);

    // ---- CSR build (independent of the GEMM) ----
    scan_block_kernel<<<SCAN_NB, SCAN_B>>>();
    scan_bsums_kernel<<<1, 32>>>();
    scan_add_kernel<<<SCAN_NB, SCAN_B>>>();
    fill_self_kernel<<<cdiv(N_NODES, T), T>>>();
    fill_edges_kernel<<<cdiv(N_EDGES, T), T>>>(src, dst);

    // ---- GCN layer 0 gather, then layers 1-2 ----
    gcn_gather_kernel<<<warp_nodes_blocks, T>>>(
        p_t, gcn_b, bn_g, bn_bt, bn_m, bn_v, 0);
    for (int layer = 1; layer < 3; layer++) {
        gemm_mma<128, false><<<dim3(mtiles, 1), 256, SMEM_BYTES>>>(
            p_h, gcn_W + (size_t)layer * 128 * 128, p_t, nullptr, nullptr, nullptr, nullptr);
        gcn_gather_kernel<<<warp_nodes_blocks, T>>>(
            p_t, gcn_b + layer * 128, bn_g + layer * 128, bn_bt + layer * 128,
            bn_m + layer * 128, bn_v + layer * 128, 1);
    }

    // ---- GAT ----
    gemm_mma<512, true><<<dim3(mtiles, 4), 256, SMEM_BYTES>>>(
        p_h, gat_W, p_hh, att_s, att_d, p_as, p_ad);
    gat_agg_kernel<<<warp_nodes_blocks, T>>>(p_hh, gat_b);

    // ---- pool + classifier ----
    pool_mlp_kernel<<<N_GRAPHS, 128>>>(batch, c1W, c1b, c2W, c2b, c3W, c3b, out);
}

// round 16
// speedup vs baseline: 1.4322x; 1.3424x over previous
#include <cuda_runtime.h>
#include <cuda_bf16.h>
#include <cuda_fp16.h>
#include <cstdint>

#define N_NODES 100000
#define N_EDGES 400000
#define HID 128
#define HEADS 4
#define N_GRAPHS 2000
#define NEG_SLOPE 0.2f
#define BN_EPS 1e-5f
#define N_ITEMS (N_EDGES + N_NODES)   // edges + self loops

#define SCAN_B 512
#define SCAN_NB ((N_NODES + SCAN_B - 1) / SCAN_B)

// ---------------- scratch (static device globals; no runtime alloc) ----------
__device__ int   g_degi[N_NODES];
__device__ float g_dinv[N_NODES];
__device__ int   g_off[N_NODES + 1];
__device__ int   g_bsum[SCAN_NB];
__device__ int   g_epos[N_NODES];
__device__ int   g_esrc[N_ITEMS];
__device__ float g_h[(size_t)N_NODES * HID];
__device__ float g_t[(size_t)N_NODES * HID];
__device__ float g_hh[(size_t)N_NODES * HEADS * HID];
__device__ float g_as[(size_t)N_NODES * HEADS];
__device__ float g_ad[(size_t)N_NODES * HEADS];

// ---------------- degree + CSR build -----------------------------------------
__global__ void deg_init_kernel() {
    int i = blockIdx.x * blockDim.x + threadIdx.x;
    if (i < N_NODES) g_degi[i] = 1;
}
__global__ void deg_accum_kernel(const int* __restrict__ dst) {
    int e = blockIdx.x * blockDim.x + threadIdx.x;
    if (e < N_EDGES) atomicAdd(&g_degi[dst[e]], 1);
}
__global__ void deg_finish_kernel() {
    int i = blockIdx.x * blockDim.x + threadIdx.x;
    if (i < N_NODES) g_dinv[i] = rsqrtf((float)g_degi[i]);
}
__global__ void scan_block_kernel() {
    __shared__ int sh[SCAN_B];
    int tid = threadIdx.x;
    int i = blockIdx.x * SCAN_B + tid;
    int v = (i < N_NODES) ? g_degi[i] : 0;
    sh[tid] = v;
    __syncthreads();
#pragma unroll
    for (int off = 1; off < SCAN_B; off <<= 1) {
        int t = (tid >= off) ? sh[tid - off] : 0;
        __syncthreads();
        sh[tid] += t;
        __syncthreads();
    }
    if (i < N_NODES) g_off[i + 1] = sh[tid];
    if (tid == SCAN_B - 1) g_bsum[blockIdx.x] = sh[tid];
}
__global__ void scan_bsums_kernel() {
    if (threadIdx.x == 0 && blockIdx.x == 0) {
        int run = 0;
        for (int b = 0; b < SCAN_NB; b++) { int t = g_bsum[b]; g_bsum[b] = run; run += t; }
    }
}
__global__ void scan_add_kernel() {
    int tid = threadIdx.x;
    int i = blockIdx.x * SCAN_B + tid;
    if (i < N_NODES) g_off[i + 1] += g_bsum[blockIdx.x];
    if (i == 0) g_off[0] = 0;
}
__global__ void fill_self_kernel() {
    int d = blockIdx.x * blockDim.x + threadIdx.x;
    if (d < N_NODES) {
        int o = g_off[d];
        g_esrc[o] = d;
        g_epos[d] = o + 1;
    }
}
__global__ void fill_edges_kernel(const int* __restrict__ src, const int* __restrict__ dst) {
    int e = blockIdx.x * blockDim.x + threadIdx.x;
    if (e < N_EDGES) {
        int pos = atomicAdd(&g_epos[dst[e]], 1);
        g_esrc[pos] = src[e];
    }
}

// ---------------- mma.sync fp16 helpers ---------------------------------------
__device__ __forceinline__ uint32_t pack_half2(float a, float b) {
    __half2 h = __floats2half2_rn(a, b);
    return *(uint32_t*)&h;
}
__device__ __forceinline__ void mma16n8k16(float* c, const uint4& a, const uint2& b) {
    asm volatile(
        "mma.sync.aligned.m16n8k16.row.col.f32.f16.f16.f32 "
        "{%0,%1,%2,%3}, {%4,%5,%6,%7}, {%8,%9}, {%0,%1,%2,%3};"
        : "+f"(c[0]), "+f"(c[1]), "+f"(c[2]), "+f"(c[3])
        : "r"(a.x), "r"(a.y), "r"(a.z), "r"(a.w), "r"(b.x), "r"(b.y));
}

// SMEM layout (uint32 units):
//  B resident: 16 n-tiles x 8 K16-steps, block = 64 u32 + 2 pad = 66  -> 8448
//  A stage x2 (K=32 chunk): 8 m-tiles x 2 K16-steps, block = 128+4 = 132 -> 2112 each
//  ATT buffer: 1024 floats
#define SB_STRIDE 66
#define SA_STRIDE 132
#define SM_B   0
#define SM_A0  8448
#define SM_A1  (8448 + 2112)
#define SM_ATT (8448 + 4224)
#define SMEM_U32 (SM_ATT + 1024)
#define SMEM_BYTES (SMEM_U32 * 4)          // 54784 B

// ---------------- tensor-core GEMM:  Out[N,C] = A[N,128] @ W[128,C] ----------
// CTA: 128 rows x 128 cols. 256 threads, 2 CTAs/SM. fp16 operands, fp32 accum.
// B fully SMEM-resident; A double-buffered in 4 K-chunks of 32.
template <int C, bool FUSE_ATT>
__global__ void __launch_bounds__(256, 2) gemm_mma(
    const float* __restrict__ A, const float* __restrict__ W, float* __restrict__ Out,
    const float* __restrict__ att_src, const float* __restrict__ att_dst,
    float* __restrict__ as_out, float* __restrict__ ad_out) {
    extern __shared__ uint32_t smem[];
    const int tid = threadIdx.x;
    const int wid = tid >> 5;
    const int lane = tid & 31;
    const int g = lane >> 2;      // group id 0..7
    const int tig = lane & 3;     // thread in group
    const int wm = wid & 1;       // warp row block (0/1 -> rows 0/64)
    const int wn = wid >> 1;      // warp col block (0..3 -> cols *32)
    const int row0 = blockIdx.x * 128;
    const int cb = blockIdx.y * 128;

    // ---- stage B (128 k x 128 n) as fp16 fragments ----
    // frag map: b0 = (k=2tig..+1, n=g), b1 = (k=2tig+8..+9, n=g)
#pragma unroll
    for (int it = 0; it < 16; it++) {
        int f4 = tid + it * 256;
        int k = f4 >> 5, nq = f4 & 31;
        float4 v = *(const float4*)&W[(size_t)k * C + cb + nq * 4];
        int ksB = k >> 4;
        int R = (k >> 3) & 1;
        int hoff = k & 1;
        int kl = (k & 7) >> 1;
        int n0 = nq * 4;
        int nt = n0 >> 3;
        __half* bp = (__half*)(smem + SM_B);
        float vv[4] = {v.x, v.y, v.z, v.w};
#pragma unroll
        for (int j = 0; j < 4; j++) {
            int L = ((n0 + j) & 7) * 4 + kl;
            bp[(((nt * 8 + ksB) * SB_STRIDE) + L * 2 + R) * 2 + hoff] = __float2half_rn(vv[j]);
        }
    }

    // ---- A chunk helpers (K chunk = 32 = 8 float4 per row) ----
    float4 aR[4];
    auto ldgA = [&](int kc) {
#pragma unroll
        for (int it = 0; it < 4; it++) {
            int f4 = tid + it * 256;
            int row = f4 >> 3, kq = f4 & 7;
            int grow = row0 + row;
            aR[it] = (grow < N_NODES)
                ? *(const float4*)&A[(size_t)grow * 128 + kc * 32 + kq * 4]
                : make_float4(0.f, 0.f, 0.f, 0.f);
        }
    };
    // frag map: a0=(g,2tig±) a1=(g+8,2tig±) a2=(g,2tig+8±) a3=(g+8,2tig+8±)
    auto stsA = [&](int st) {
        uint32_t* base = smem + (st ? SM_A1 : SM_A0);
#pragma unroll
        for (int it = 0; it < 4; it++) {
            int f4 = tid + it * 256;
            int row = f4 >> 3, kq = f4 & 7;
            int mt = row >> 4, r = row & 15, gg = r & 7, hi = r >> 3;
            int ksl = kq >> 2;             // K16 step within chunk
            int kin = (kq & 3) * 4;        // k offset within the K16 step
            int L = gg * 4 + ((kin & 7) >> 1);
            int R = hi + 2 * (kin >> 3);
            uint32_t* bp = base + (mt * 2 + ksl) * SA_STRIDE;
            bp[L * 4 + R] = pack_half2(aR[it].x, aR[it].y);
            bp[(L + 1) * 4 + R] = pack_half2(aR[it].z, aR[it].w);
        }
    };

    float acc[4][4][4];
#pragma unroll
    for (int mt = 0; mt < 4; mt++)
#pragma unroll
        for (int nt = 0; nt < 4; nt++)
#pragma unroll
            for (int j = 0; j < 4; j++) acc[mt][nt][j] = 0.f;

    auto compute = [&](int kc) {
        uint32_t* abase = smem + ((kc & 1) ? SM_A1 : SM_A0);
#pragma unroll
        for (int ks = 0; ks < 2; ks++) {
            uint4 a[4];
            uint2 b[4];
#pragma unroll
            for (int mt = 0; mt < 4; mt++)
                a[mt] = *(uint4*)&abase[((wm * 4 + mt) * 2 + ks) * SA_STRIDE + lane * 4];
#pragma unroll
            for (int nt = 0; nt < 4; nt++)
                b[nt] = *(uint2*)&smem[SM_B + ((wn * 4 + nt) * 8 + kc * 2 + ks) * SB_STRIDE + lane * 2];
#pragma unroll
            for (int mt = 0; mt < 4; mt++)
#pragma unroll
                for (int nt = 0; nt < 4; nt++)
                    mma16n8k16(acc[mt][nt], a[mt], b[nt]);
        }
    };

    // ---- pipelined mainloop: LDG(kc+2) overlaps compute(kc+1) ----
    ldgA(0);
    stsA(0);
    ldgA(1);
    __syncthreads();
#pragma unroll
    for (int kc = 0; kc < 4; kc++) {
        compute(kc);
        if (kc < 3) {
            stsA((kc + 1) & 1);
            __syncthreads();
            if (kc < 2) ldgA(kc + 2);
        }
    }

    // ---- store C ----
#pragma unroll
    for (int mt = 0; mt < 4; mt++) {
        int r_lo = row0 + wm * 64 + mt * 16 + g;
        int r_hi = r_lo + 8;
#pragma unroll
        for (int nt = 0; nt < 4; nt++) {
            int col = cb + wn * 32 + nt * 8 + 2 * tig;
            if (r_lo < N_NODES)
                *(float2*)&Out[(size_t)r_lo * C + col] = make_float2(acc[mt][nt][0], acc[mt][nt][1]);
            if (r_hi < N_NODES)
                *(float2*)&Out[(size_t)r_hi * C + col] = make_float2(acc[mt][nt][2], acc[mt][nt][3]);
        }
    }

    if (FUSE_ATT) {
        const int head = blockIdx.y;
        const float* Ws = att_src + head * 128;
        const float* Wd = att_dst + head * 128;
        float* att = (float*)(smem + SM_ATT);
#pragma unroll
        for (int mt = 0; mt < 4; mt++) {
            float ss0 = 0.f, sd0 = 0.f, ss1 = 0.f, sd1 = 0.f;
#pragma unroll
            for (int nt = 0; nt < 4; nt++) {
                int col = wn * 32 + nt * 8 + 2 * tig;
                float w0s = Ws[col], w1s = Ws[col + 1];
                float w0d = Wd[col], w1d = Wd[col + 1];
                ss0 += acc[mt][nt][0] * w0s + acc[mt][nt][1] * w1s;
                sd0 += acc[mt][nt][0] * w0d + acc[mt][nt][1] * w1d;
                ss1 += acc[mt][nt][2] * w0s + acc[mt][nt][3] * w1s;
                sd1 += acc[mt][nt][2] * w0d + acc[mt][nt][3] * w1d;
            }
#pragma unroll
            for (int o = 1; o <= 2; o <<= 1) {
                ss0 += __shfl_xor_sync(0xffffffffu, ss0, o);
                sd0 += __shfl_xor_sync(0xffffffffu, sd0, o);
                ss1 += __shfl_xor_sync(0xffffffffu, ss1, o);
                sd1 += __shfl_xor_sync(0xffffffffu, sd1, o);
            }
            if (tig == 0) {
                int r_lo = wm * 64 + mt * 16 + g;
                int r_hi = r_lo + 8;
                att[(r_lo * 4 + wn) * 2 + 0] = ss0;
                att[(r_lo * 4 + wn) * 2 + 1] = sd0;
                att[(r_hi * 4 + wn) * 2 + 0] = ss1;
                att[(r_hi * 4 + wn) * 2 + 1] = sd1;
            }
        }
        __syncthreads();
        if (tid < 128) {
            int grow = row0 + tid;
            if (grow < N_NODES) {
                float ss = 0.f, sd = 0.f;
#pragma unroll
                for (int w = 0; w < 4; w++) {
                    ss += att[(tid * 4 + w) * 2 + 0];
                    sd += att[(tid * 4 + w) * 2 + 1];
                }
                as_out[grow * HEADS + head] = ss;
                ad_out[grow * HEADS + head] = sd;
            }
        }
    }
}

// ---------------- GCN gather (CSR) + bias + BN + ReLU + residual -------------
__global__ void gcn_gather_kernel(const float* __restrict__ t,
                                  const float* __restrict__ b, const float* __restrict__ gamma,
                                  const float* __restrict__ beta, const float* __restrict__ mean,
                                  const float* __restrict__ var, int residual) {
    int warp = (blockIdx.x * blockDim.x + threadIdx.x) >> 5;
    int lane = threadIdx.x & 31;
    if (warp >= N_NODES) return;
    const int d = warp;
    const float dd = g_dinv[d];
    const int beg = g_off[d], end = g_off[d + 1];
    const int c = lane * 4;
    float4 acc = make_float4(0.f, 0.f, 0.f, 0.f);
    for (int i = beg; i < end; i++) {
        int s = g_esrc[i];
        float w = dd * g_dinv[s];
        float4 v = *(const float4*)&t[(size_t)s * HID + c];
        acc.x += v.x * w; acc.y += v.y * w; acc.z += v.z * w; acc.w += v.w * w;
    }
    float4 bb = *(const float4*)&b[c];
    float4 mm = *(const float4*)&mean[c];
    float4 vv = *(const float4*)&var[c];
    float4 gg = *(const float4*)&gamma[c];
    float4 be = *(const float4*)&beta[c];
    float4 r;
    r.x = fmaxf((acc.x + bb.x - mm.x) * rsqrtf(vv.x + BN_EPS) * gg.x + be.x, 0.f);
    r.y = fmaxf((acc.y + bb.y - mm.y) * rsqrtf(vv.y + BN_EPS) * gg.y + be.y, 0.f);
    r.z = fmaxf((acc.z + bb.z - mm.z) * rsqrtf(vv.z + BN_EPS) * gg.z + be.z, 0.f);
    r.w = fmaxf((acc.w + bb.w - mm.w) * rsqrtf(vv.w + BN_EPS) * gg.w + be.w, 0.f);
    float* hp = &g_h[(size_t)d * HID + c];
    if (residual) {
        float4 hv = *(const float4*)hp;
        r.x += hv.x; r.y += hv.y; r.z += hv.z; r.w += hv.w;
    }
    *(float4*)hp = r;
}

__device__ __forceinline__ float leaky(float x) { return x > 0.f ? x : NEG_SLOPE * x; }

// ---------------- GAT: softmax (max cancels) + weighted gather + bias --------
__global__ void gat_agg_kernel(const float* __restrict__ hh, const float* __restrict__ gat_b) {
    int warp = (blockIdx.x * blockDim.x + threadIdx.x) >> 5;
    int lane = threadIdx.x & 31;
    if (warp >= N_NODES) return;
    const int d = warp;
    const int beg = g_off[d], end = g_off[d + 1];
    const float4 ad4 = *(const float4*)&g_ad[(size_t)d * HEADS];

    float4 ds = make_float4(0.f, 0.f, 0.f, 0.f);
    for (int i = beg + lane; i < end; i += 32) {
        int s = g_esrc[i];
        float4 as4 = *(const float4*)&g_as[(size_t)s * HEADS];
        ds.x += expf(leaky(as4.x + ad4.x));
        ds.y += expf(leaky(as4.y + ad4.y));
        ds.z += expf(leaky(as4.z + ad4.z));
        ds.w += expf(leaky(as4.w + ad4.w));
    }
#pragma unroll
    for (int o = 16; o; o >>= 1) {
        ds.x += __shfl_xor_sync(0xffffffffu, ds.x, o);
        ds.y += __shfl_xor_sync(0xffffffffu, ds.y, o);
        ds.z += __shfl_xor_sync(0xffffffffu, ds.z, o);
        ds.w += __shfl_xor_sync(0xffffffffu, ds.w, o);
    }
    float4 rcp;
    rcp.x = 0.25f / (ds.x + 1e-16f);
    rcp.y = 0.25f / (ds.y + 1e-16f);
    rcp.z = 0.25f / (ds.z + 1e-16f);
    rcp.w = 0.25f / (ds.w + 1e-16f);

    const int c = lane * 4;
    float4 acc = make_float4(0.f, 0.f, 0.f, 0.f);
    for (int i = beg; i < end; i++) {
        int s = g_esrc[i];
        float4 as4 = *(const float4*)&g_as[(size_t)s * HEADS];
        float a0 = expf(leaky(as4.x + ad4.x)) * rcp.x;
        float a1 = expf(leaky(as4.y + ad4.y)) * rcp.y;
        float a2 = expf(leaky(as4.z + ad4.z)) * rcp.z;
        float a3 = expf(leaky(as4.w + ad4.w)) * rcp.w;
        const float* p = hh + (size_t)s * (HEADS * HID) + c;
        float4 v0 = *(const float4*)p;
        float4 v1 = *(const float4*)(p + HID);
        float4 v2 = *(const float4*)(p + 2 * HID);
        float4 v3 = *(const float4*)(p + 3 * HID);
        acc.x += a0 * v0.x + a1 * v1.x + a2 * v2.x + a3 * v3.x;
        acc.y += a0 * v0.y + a1 * v1.y + a2 * v2.y + a3 * v3.y;
        acc.z += a0 * v0.z + a1 * v1.z + a2 * v2.z + a3 * v3.z;
        acc.w += a0 * v0.w + a1 * v1.w + a2 * v2.w + a3 * v3.w;
    }
    float4 bv = *(const float4*)&gat_b[c];
    float* hp = &g_h[(size_t)d * HID + c];
    float4 hv = *(const float4*)hp;
    hv.x += acc.x + bv.x; hv.y += acc.y + bv.y;
    hv.z += acc.z + bv.z; hv.w += acc.w + bv.w;
    *(float4*)hp = hv;
}

// ---------------- pool (sorted batch -> ranges) + MLP ------------------------
__global__ void pool_mlp_kernel(const int* __restrict__ batch,
                                const float* __restrict__ c1W, const float* __restrict__ c1b,
                                const float* __restrict__ c2W, const float* __restrict__ c2b,
                                const float* __restrict__ c3W, const float* __restrict__ c3b,
                                float* __restrict__ out) {
    const int g = blockIdx.x;
    const int tid = threadIdx.x;   // 128 threads
    __shared__ int sbeg, send;
    __shared__ float gv[128];
    __shared__ float z1[64];
    __shared__ float z2[32];
    if (tid == 0) {
        int lo = 0, hi = N_NODES;
        while (lo < hi) { int mid = (lo + hi) >> 1; if (batch[mid] < g) lo = mid + 1; else hi = mid; }
        sbeg = lo;
        lo = sbeg; hi = N_NODES;
        while (lo < hi) { int mid = (lo + hi) >> 1; if (batch[mid] < g + 1) lo = mid + 1; else hi = mid; }
        send = lo;
    }
    __syncthreads();
    const int beg = sbeg, end = send;
    float s = 0.f;
    for (int r = beg; r < end; r++) s += g_h[(size_t)r * HID + tid];
    float cnt = fmaxf((float)(end - beg), 1.0f);
    gv[tid] = s / cnt;
    __syncthreads();
    if (tid < 64) {
        float z = c1b[tid];
#pragma unroll 8
        for (int k = 0; k < 128; k++) z += gv[k] * c1W[k * 64 + tid];
        z1[tid] = fmaxf(z, 0.f);
    }
    __syncthreads();
    if (tid < 32) {
        float z = c2b[tid];
#pragma unroll 8
        for (int k = 0; k < 64; k++) z += z1[k] * c2W[k * 32 + tid];
        z2[tid] = fmaxf(z, 0.f);
        __syncwarp();
        float p = z2[tid] * c3W[tid];
#pragma unroll
        for (int o = 16; o; o >>= 1) p += __shfl_xor_sync(0xffffffffu, p, o);
        if (tid == 0) out[g] = p + c3b[0];
    }
}

// -----------------------------------------------------------------------------
static inline int cdiv(long long a, int b) { return (int)((a + b - 1) / b); }

extern "C" void kernel_launch(void* const* d_in, const int* in_sizes, int n_in,
                              void* d_out, int out_size) {
    const float* x      = (const float*)d_in[0];
    const int*   ei     = (const int*)d_in[1];
    const int*   batch  = (const int*)d_in[2];
    const float* gcn_W  = (const float*)d_in[3];
    const float* gcn_b  = (const float*)d_in[4];
    const float* bn_g   = (const float*)d_in[5];
    const float* bn_bt  = (const float*)d_in[6];
    const float* bn_m   = (const float*)d_in[7];
    const float* bn_v   = (const float*)d_in[8];
    const float* gat_W  = (const float*)d_in[9];
    const float* att_s  = (const float*)d_in[10];
    const float* att_d  = (const float*)d_in[11];
    const float* gat_b  = (const float*)d_in[12];
    const float* c1W    = (const float*)d_in[13];
    const float* c1b    = (const float*)d_in[14];
    const float* c2W    = (const float*)d_in[15];
    const float* c2b    = (const float*)d_in[16];
    const float* c3W    = (const float*)d_in[17];
    const float* c3b    = (const float*)d_in[18];
    float* out = (float*)d_out;

    const int* src = ei;
    const int* dst = ei + N_EDGES;
    const int T = 256;

    float *p_h, *p_t, *p_hh, *p_as, *p_ad;
    cudaGetSymbolAddress((void**)&p_h, g_h);
    cudaGetSymbolAddress((void**)&p_t, g_t);
    cudaGetSymbolAddress((void**)&p_hh, g_hh);
    cudaGetSymbolAddress((void**)&p_as, g_as);
    cudaGetSymbolAddress((void**)&p_ad, g_ad);

    cudaFuncSetAttribute(gemm_mma<128, false>, cudaFuncAttributeMaxDynamicSharedMemorySize, SMEM_BYTES);
    cudaFuncSetAttribute(gemm_mma<512, true>,  cudaFuncAttributeMaxDynamicSharedMemorySize, SMEM_BYTES);

    const int warp_nodes_blocks = cdiv((long long)N_NODES * 32, T);
    const int mtiles = cdiv(N_NODES, 128);

    // ---- degrees (1-3), then GCN layer-0 GEMM as launch #4 (profiled) ----
    deg_init_kernel<<<cdiv(N_NODES, T), T>>>();
    deg_accum_kernel<<<cdiv(N_EDGES, T), T>>>(dst);
    deg_finish_kernel<<<cdiv(N_NODES, T), T>>>();
    gemm_mma<128, false><<<dim3(mtiles, 1), 256, SMEM_BYTES>>>(
        x, gcn_W, p_t, nullptr, nullptr, nullptr, nullptr);

    // ---- CSR build (independent of the GEMM) ----
    scan_block_kernel<<<SCAN_NB, SCAN_B>>>();
    scan_bsums_kernel<<<1, 32>>>();
    scan_add_kernel<<<SCAN_NB, SCAN_B>>>();
    fill_self_kernel<<<cdiv(N_NODES, T), T>>>();
    fill_edges_kernel<<<cdiv(N_EDGES, T), T>>>(src, dst);

    // ---- GCN layer 0 gather, then layers 1-2 ----
    gcn_gather_kernel<<<warp_nodes_blocks, T>>>(
        p_t, gcn_b, bn_g, bn_bt, bn_m, bn_v, 0);
    for (int layer = 1; layer < 3; layer++) {
        gemm_mma<128, false><<<dim3(mtiles, 1), 256, SMEM_BYTES>>>(
            p_h, gcn_W + (size_t)layer * 128 * 128, p_t, nullptr, nullptr, nullptr, nullptr);
        gcn_gather_kernel<<<warp_nodes_blocks, T>>>(
            p_t, gcn_b + layer * 128, bn_g + layer * 128, bn_bt + layer * 128,
            bn_m + layer * 128, bn_v + layer * 128, 1);
    }

    // ---- GAT ----
    gemm_mma<512, true><<<dim3(mtiles, 4), 256, SMEM_BYTES>>>(
        p_h, gat_W, p_hh, att_s, att_d, p_as, p_ad);
    gat_agg_kernel<<<warp_nodes_blocks, T>>>(p_hh, gat_b);

    // ---- pool + classifier ----
    pool_mlp_kernel<<<N_GRAPHS, 128>>>(batch, c1W, c1b, c2W, c2b, c3W, c3b, out);
}